// round 1
// baseline (speedup 1.0000x reference)
#include <cuda_runtime.h>
#include <math.h>

// Problem constants (fixed by the reference)
#define BB 4
#define SS 2048
#define HH 1024
#define NHEADS 16
#define DHEAD 64
#define MROWS (BB * SS)        // 8192
#define TENSOR_ELEMS (MROWS * HH)  // 8,388,608 per output tensor

// Scratch (allocation-free rule: __device__ globals)
__device__ float g_ln[MROWS * HH];  // layernorm output
__device__ float g_q[MROWS * HH];   // Q projection

// ---------------------------------------------------------------------------
// Kernel 1: LayerNorm. One block per row (8192 rows), 256 threads, float4.
// ---------------------------------------------------------------------------
__global__ __launch_bounds__(256)
void ln_kernel(const float* __restrict__ x,
               const float* __restrict__ w,
               const float* __restrict__ bvec,
               float* __restrict__ y)
{
    const int row = blockIdx.x;
    const int t = threadIdx.x;
    const float4 xv = ((const float4*)(x + (size_t)row * HH))[t];

    float s  = xv.x + xv.y + xv.z + xv.w;
    float ss = xv.x * xv.x + xv.y * xv.y + xv.z * xv.z + xv.w * xv.w;
    #pragma unroll
    for (int o = 16; o > 0; o >>= 1) {
        s  += __shfl_xor_sync(0xFFFFFFFFu, s,  o);
        ss += __shfl_xor_sync(0xFFFFFFFFu, ss, o);
    }
    __shared__ float rs[8], rss[8];
    __shared__ float smu, srstd;
    const int wid = t >> 5, lane = t & 31;
    if (lane == 0) { rs[wid] = s; rss[wid] = ss; }
    __syncthreads();
    if (t == 0) {
        float a = 0.f, b2 = 0.f;
        #pragma unroll
        for (int i = 0; i < 8; i++) { a += rs[i]; b2 += rss[i]; }
        const float mu = a * (1.0f / HH);
        float var = b2 * (1.0f / HH) - mu * mu;
        smu = mu;
        srstd = rsqrtf(var + 1e-12f);
    }
    __syncthreads();
    const float mu = smu, rstd = srstd;
    const float4 wv = ((const float4*)w)[t];
    const float4 bv = ((const float4*)bvec)[t];
    float4 o;
    o.x = (xv.x - mu) * rstd * wv.x + bv.x;
    o.y = (xv.y - mu) * rstd * wv.y + bv.y;
    o.z = (xv.z - mu) * rstd * wv.z + bv.z;
    o.w = (xv.w - mu) * rstd * wv.w + bv.w;
    ((float4*)(y + (size_t)row * HH))[t] = o;
}

// ---------------------------------------------------------------------------
// Kernel 2/4: SGEMM NT  C[M,N] = A[M,K] @ B[N,K]^T (+bias)
// BM=BN=128, BK=16, 256 threads, 8x8 per-thread tile.
// SPLIT: route output columns [0,1024)->C0 (q scratch), [1024,2048)->C1 (key),
//        [2048,3072)->C2 (value), each as [M,1024] row-major.
// ---------------------------------------------------------------------------
template<bool SPLIT>
__global__ __launch_bounds__(256)
void sgemm_nt(const float* __restrict__ A, const float* __restrict__ Bw,
              const float* __restrict__ bias,
              float* __restrict__ C0, float* __restrict__ C1, float* __restrict__ C2,
              int M, int N, int K)
{
    constexpr int BM = 128, BN = 128, BK = 16, PAD = 4;
    __shared__ float As[BK][BM + PAD];
    __shared__ float Bs[BK][BN + PAD];

    const int bm = blockIdx.y * BM;
    const int bn = blockIdx.x * BN;
    const int tid = threadIdx.x;

    const int lr = tid >> 2;        // 0..63 (row within half-tile)
    const int lc = (tid & 3) * 4;   // k offset: 0,4,8,12
    const int tr = (tid >> 4) * 8;  // 0..120
    const int tc = (tid & 15) * 8;  // 0..120

    float acc[8][8];
    #pragma unroll
    for (int i = 0; i < 8; i++)
        #pragma unroll
        for (int j = 0; j < 8; j++) acc[i][j] = 0.f;

    for (int k0 = 0; k0 < K; k0 += BK) {
        #pragma unroll
        for (int i = 0; i < 2; i++) {
            const int r = lr + i * 64;
            const float4 v = *(const float4*)(A  + (size_t)(bm + r) * K + k0 + lc);
            As[lc + 0][r] = v.x; As[lc + 1][r] = v.y;
            As[lc + 2][r] = v.z; As[lc + 3][r] = v.w;
            const float4 u = *(const float4*)(Bw + (size_t)(bn + r) * K + k0 + lc);
            Bs[lc + 0][r] = u.x; Bs[lc + 1][r] = u.y;
            Bs[lc + 2][r] = u.z; Bs[lc + 3][r] = u.w;
        }
        __syncthreads();
        #pragma unroll
        for (int kk = 0; kk < BK; kk++) {
            float ra[8], rb[8];
            #pragma unroll
            for (int i = 0; i < 8; i++) ra[i] = As[kk][tr + i];
            #pragma unroll
            for (int j = 0; j < 8; j++) rb[j] = Bs[kk][tc + j];
            #pragma unroll
            for (int i = 0; i < 8; i++)
                #pragma unroll
                for (int j = 0; j < 8; j++)
                    acc[i][j] = fmaf(ra[i], rb[j], acc[i][j]);
        }
        __syncthreads();
    }

    #pragma unroll
    for (int i = 0; i < 8; i++) {
        const int gm = bm + tr + i;
        #pragma unroll
        for (int j = 0; j < 8; j++) {
            const int gn = bn + tc + j;
            float v = acc[i][j];
            if (bias) v += bias[gn];
            if (SPLIT) {
                const int sec = gn >> 10;
                const int col = gn & 1023;
                float* Cp = (sec == 0) ? C0 : ((sec == 1) ? C1 : C2);
                Cp[(size_t)gm * 1024 + col] = v;
            } else {
                C0[(size_t)gm * N + gn] = v;
            }
        }
    }
}

// ---------------------------------------------------------------------------
// Kernel 3: fp32 flash attention.
// grid (S/128, NHEADS, BB); 128 threads; each thread owns one q row.
// K/V read from d_out key/value regions ([B,S,H], head h = cols h*64..h*64+63).
// ---------------------------------------------------------------------------
__global__ __launch_bounds__(128)
void attn_kernel(const float* __restrict__ Q, const float* __restrict__ Kk,
                 const float* __restrict__ Vv, const float* __restrict__ mask,
                 float* __restrict__ Ctx)
{
    const int b = blockIdx.z, h = blockIdx.y, qt = blockIdx.x;
    const int t = threadIdx.x;
    const int qrow = qt * 128 + t;

    float q[DHEAD];
    {
        const float4* qp = (const float4*)(Q + ((size_t)(b * SS + qrow) * HH + h * DHEAD));
        #pragma unroll
        for (int i = 0; i < 16; i++) {
            const float4 v = qp[i];
            q[4 * i + 0] = v.x; q[4 * i + 1] = v.y;
            q[4 * i + 2] = v.z; q[4 * i + 3] = v.w;
        }
    }

    float acc[DHEAD];
    #pragma unroll
    for (int d = 0; d < DHEAD; d++) acc[d] = 0.f;
    float mrow = -INFINITY, lrow = 0.f;

    __shared__ float Ks[32][DHEAD];
    __shared__ float Vs[32][DHEAD];
    __shared__ float Ms[32];
    const float scale = 0.125f;  // 1/sqrt(64)

    for (int kt = 0; kt < SS; kt += 32) {
        // cooperative load of 32x64 K and V tiles (512 float4 each, 4/thread)
        #pragma unroll
        for (int i = 0; i < 4; i++) {
            const int f = t + i * 128;
            const int r = f >> 4, c = f & 15;
            const size_t base = (size_t)(b * SS + kt + r) * HH + h * DHEAD + c * 4;
            *(float4*)&Ks[r][c * 4] = *(const float4*)(Kk + base);
            *(float4*)&Vs[r][c * 4] = *(const float4*)(Vv + base);
        }
        if (t < 32) Ms[t] = mask[b * SS + kt + t];
        __syncthreads();

        float sc[32];
        #pragma unroll
        for (int j = 0; j < 32; j++) {
            float s = 0.f;
            const float4* k4 = (const float4*)Ks[j];
            #pragma unroll
            for (int d4 = 0; d4 < 16; d4++) {
                const float4 kv = k4[d4];
                s = fmaf(q[4 * d4 + 0], kv.x, s);
                s = fmaf(q[4 * d4 + 1], kv.y, s);
                s = fmaf(q[4 * d4 + 2], kv.z, s);
                s = fmaf(q[4 * d4 + 3], kv.w, s);
            }
            sc[j] = s * scale + Ms[j];
        }

        float tmax = mrow;
        #pragma unroll
        for (int j = 0; j < 32; j++) tmax = fmaxf(tmax, sc[j]);
        const float corr = __expf(mrow - tmax);
        lrow *= corr;
        #pragma unroll
        for (int d = 0; d < DHEAD; d++) acc[d] *= corr;

        #pragma unroll
        for (int j = 0; j < 32; j++) {
            const float p = __expf(sc[j] - tmax);
            lrow += p;
            const float4* v4 = (const float4*)Vs[j];
            #pragma unroll
            for (int d4 = 0; d4 < 16; d4++) {
                const float4 vv = v4[d4];
                acc[4 * d4 + 0] = fmaf(p, vv.x, acc[4 * d4 + 0]);
                acc[4 * d4 + 1] = fmaf(p, vv.y, acc[4 * d4 + 1]);
                acc[4 * d4 + 2] = fmaf(p, vv.z, acc[4 * d4 + 2]);
                acc[4 * d4 + 3] = fmaf(p, vv.w, acc[4 * d4 + 3]);
            }
        }
        mrow = tmax;
        __syncthreads();
    }

    const float inv = 1.0f / lrow;
    float4* op = (float4*)(Ctx + ((size_t)(b * SS + qrow) * HH + h * DHEAD));
    #pragma unroll
    for (int i = 0; i < 16; i++) {
        float4 o;
        o.x = acc[4 * i + 0] * inv;
        o.y = acc[4 * i + 1] * inv;
        o.z = acc[4 * i + 2] * inv;
        o.w = acc[4 * i + 3] * inv;
        op[i] = o;
    }
}

// ---------------------------------------------------------------------------
// Launch
// ---------------------------------------------------------------------------
extern "C" void kernel_launch(void* const* d_in, const int* in_sizes, int n_in,
                              void* d_out, int out_size)
{
    const float* input = (const float*)d_in[0];
    const float* mask  = (const float*)d_in[1];
    const float* nw    = (const float*)d_in[2];
    const float* nb    = (const float*)d_in[3];
    const float* qkvw  = (const float*)d_in[4];
    const float* qkvb  = (const float*)d_in[5];
    const float* ow    = (const float*)d_in[6];

    float* out     = (float*)d_out;                 // [B,S,H] output
    float* key_out = out + (size_t)TENSOR_ELEMS;    // [B,S,H] key_layer
    float* val_out = out + (size_t)2 * TENSOR_ELEMS;// [B,S,H] value_layer
    float* ctx_out = out + (size_t)3 * TENSOR_ELEMS;// [B,S,H] context_layer

    float *ln_ptr = nullptr, *q_ptr = nullptr;
    cudaGetSymbolAddress((void**)&ln_ptr, g_ln);
    cudaGetSymbolAddress((void**)&q_ptr,  g_q);

    // 1) LayerNorm
    ln_kernel<<<MROWS, 256>>>(input, nw, nb, ln_ptr);

    // 2) QKV GEMM: [8192,1024] x [3072,1024]^T, split into q scratch / key / value
    {
        dim3 grid(3072 / 128, MROWS / 128);
        sgemm_nt<true><<<grid, 256>>>(ln_ptr, qkvw, qkvb,
                                      q_ptr, key_out, val_out,
                                      MROWS, 3 * HH, HH);
    }

    // 3) Flash attention -> context_layer
    {
        dim3 grid(SS / 128, NHEADS, BB);
        attn_kernel<<<grid, 128>>>(q_ptr, key_out, val_out, mask, ctx_out);
    }

    // 4) Output projection: [8192,1024] x [1024,1024]^T -> output
    {
        dim3 grid(1024 / 128, MROWS / 128);
        sgemm_nt<false><<<grid, 256>>>(ctx_out, ow, nullptr,
                                       out, nullptr, nullptr,
                                       MROWS, HH, HH);
    }
}